// round 15
// baseline (speedup 1.0000x reference)
#include <cuda_runtime.h>
#include <cuda_bf16.h>

// Problem constants (fixed by setup_inputs)
#define BATCH 32
#define NNODE 512
#define DIM   256
#define NHEAD 8
#define HDIM  32
#define WPR   16            // u32 words per mask row (512/32)
#define GWORDS (NNODE*WPR)  // 8192 words per graph
#define NTOT  (BATCH*NNODE)

// ---------------- scratch (static device globals; no allocations) ----------------
__device__ float     g_inv[NTOT];
__device__ float     g_scale[NTOT];
__device__ unsigned  g_maskA[BATCH*GWORDS];
__device__ unsigned  g_maskB[BATCH*GWORDS];
__device__ float     g_qkv[(size_t)NTOT*3*DIM];   // P = x @ Win^T (unscaled, no bias)
__device__ float     g_att[(size_t)NTOT*DIM];
__device__ float     g_po[(size_t)512*512*32];    // split-K partial O (unnormalized)
__device__ float     g_pm[512*512];               // split-K partial row max (log2)
__device__ float     g_pl[512*512];               // split-K partial row sum

static __device__ __forceinline__ float warp_sum(float v) {
#pragma unroll
    for (int o = 16; o; o >>= 1) v += __shfl_xor_sync(0xffffffffu, v, o);
    return v;
}
static __device__ __forceinline__ float ex2f(float x) {
    float y; asm("ex2.approx.f32 %0, %1;" : "=f"(y) : "f"(x)); return y;
}

// ---------------- 1. per-node inverse norms (one warp per node) ----------------
__global__ void norm_kernel(const float* __restrict__ x, float* __restrict__ inv) {
    int node = (blockIdx.x * blockDim.x + threadIdx.x) >> 5;
    int lane = threadIdx.x & 31;
    const float4* xr = (const float4*)(x + (size_t)node * DIM);
    float4 a = xr[lane];
    float s = a.x*a.x + a.y*a.y + a.z*a.z + a.w*a.w;
    a = xr[lane + 32];
    s += a.x*a.x + a.y*a.y + a.z*a.z + a.w*a.w;
    s = warp_sum(s);
    if (lane == 0) inv[node] = 1.0f / fmaxf(sqrtf(s), 1e-8f);
}

// ---------------- 2. zero mask ----------------
__global__ void zero_kernel(unsigned* p, int n) {
    for (int i = blockIdx.x * blockDim.x + threadIdx.x; i < n; i += gridDim.x * blockDim.x)
        p[i] = 0u;
}

// ---------------- 3. per-edge cosine sim -> mask bits (8 lanes per edge) ----------------
__global__ void edge_kernel(const float* __restrict__ x, const int* __restrict__ ei,
                            const float* __restrict__ inv, unsigned* __restrict__ mask, int E) {
    int t = blockIdx.x * blockDim.x + threadIdx.x;
    int e = t >> 3, sub = t & 7;
    if (e >= E) return;
    int s = ei[e], d = ei[E + e];
    const float4* xs = (const float4*)(x + (size_t)s * DIM) + sub;
    const float4* xd = (const float4*)(x + (size_t)d * DIM) + sub;
    float acc = 0.0f;
#pragma unroll
    for (int i = 0; i < 8; i++) {
        float4 a = xs[i * 8];
        float4 b = xd[i * 8];
        acc += a.x*b.x + a.y*b.y + a.z*b.z + a.w*b.w;
    }
    acc += __shfl_xor_sync(0xffffffffu, acc, 1);
    acc += __shfl_xor_sync(0xffffffffu, acc, 2);
    acc += __shfl_xor_sync(0xffffffffu, acc, 4);
    if (sub == 0) {
        float sim = acc * inv[s] * inv[d];
        if (sim > 0.1f) {
            int bg = s >> 9, i = s & 511, j = d & 511;
            unsigned* mb = mask + ((size_t)bg << 13);
            atomicOr(&mb[i * WPR + (j >> 5)], 1u << (j & 31));
            atomicOr(&mb[j * WPR + (i >> 5)], 1u << (i & 31));
        }
    }
}

// ---------------- 4. one closure step: dst = src OR src*src ----------------
__global__ void closure_kernel(const unsigned* __restrict__ src, unsigned* __restrict__ dst) {
    __shared__ unsigned sA[GWORDS];           // 32 KB
    int g = blockIdx.x >> 5, ch = blockIdx.x & 31;
    const unsigned* A = src + (size_t)g * GWORDS;
    for (int i = threadIdx.x; i < GWORDS; i += 256) sA[i] = A[i];
    __syncthreads();
    int warp = threadIdx.x >> 5, lane = threadIdx.x & 31, hl = lane & 15;
    bool hi = lane >= 16;
    for (int r = warp; r < 16; r += 8) {
        int i = ch * 16 + r;
        unsigned rowW = sA[i * WPR + hl];
        unsigned acc = rowW;
        for (int w = 0; w < WPR; w++) {
            unsigned bits = __shfl_sync(0xffffffffu, rowW, w);
            while (bits) {
                int k1 = __ffs(bits) - 1; bits &= bits - 1;
                int k2 = -1;
                if (bits) { k2 = __ffs(bits) - 1; bits &= bits - 1; }
                int k = hi ? k2 : k1;
                if (k >= 0) acc |= sA[((w << 5) + k) * WPR + hl];
            }
        }
        acc |= __shfl_xor_sync(0xffffffffu, acc, 16);
        if (!hi) dst[(size_t)g * GWORDS + i * WPR + hl] = acc;
    }
}

// ---------------- 5. final closure step fused with degree->scale ----------------
__global__ void closure_deg_kernel(const unsigned* __restrict__ src, float* __restrict__ scl) {
    __shared__ unsigned sA[GWORDS];           // 32 KB
    int g = blockIdx.x >> 5, ch = blockIdx.x & 31;
    const unsigned* A = src + (size_t)g * GWORDS;
    for (int i = threadIdx.x; i < GWORDS; i += 256) sA[i] = A[i];
    __syncthreads();
    int warp = threadIdx.x >> 5, lane = threadIdx.x & 31, hl = lane & 15;
    bool hi = lane >= 16;
    for (int r = warp; r < 16; r += 8) {
        int i = ch * 16 + r;
        unsigned rowW = sA[i * WPR + hl];
        unsigned acc = rowW;
        for (int w = 0; w < WPR; w++) {
            unsigned bits = __shfl_sync(0xffffffffu, rowW, w);
            while (bits) {
                int k1 = __ffs(bits) - 1; bits &= bits - 1;
                int k2 = -1;
                if (bits) { k2 = __ffs(bits) - 1; bits &= bits - 1; }
                int k = hi ? k2 : k1;
                if (k >= 0) acc |= sA[((w << 5) + k) * WPR + hl];
            }
        }
        acc |= __shfl_xor_sync(0xffffffffu, acc, 16);
        int c = __popc(acc);
#pragma unroll
        for (int o = 16; o; o >>= 1) c += __shfl_xor_sync(0xffffffffu, c, o);
        if (lane == 0) scl[g * NNODE + i] = 1.0f + (float)(c >> 1);
    }
}

// ---- mma.sync helpers ----
static __device__ __forceinline__ void ldsm4(unsigned addr,
    unsigned& r0, unsigned& r1, unsigned& r2, unsigned& r3) {
    asm volatile("ldmatrix.sync.aligned.m8n8.x4.shared.b16 {%0,%1,%2,%3}, [%4];"
                 : "=r"(r0), "=r"(r1), "=r"(r2), "=r"(r3) : "r"(addr));
}
static __device__ __forceinline__ void mma_bf16(float* c, const unsigned* a,
                                                unsigned b0, unsigned b1) {
    asm volatile("mma.sync.aligned.m16n8k16.row.col.f32.bf16.bf16.f32 "
                 "{%0,%1,%2,%3}, {%4,%5,%6,%7}, {%8,%9}, {%0,%1,%2,%3};"
                 : "+f"(c[0]), "+f"(c[1]), "+f"(c[2]), "+f"(c[3])
                 : "r"(a[0]), "r"(a[1]), "r"(a[2]), "r"(a[3]), "r"(b0), "r"(b1));
}
static __device__ __forceinline__ void split_pack(float a, float b, unsigned& hi, unsigned& lo) {
    unsigned h;
    asm("cvt.rn.bf16x2.f32 %0, %1, %2;" : "=r"(h) : "f"(b), "f"(a));  // {hi16:b, lo16:a}
    float ar = __uint_as_float(h << 16);
    float br = __uint_as_float(h & 0xFFFF0000u);
    float la = a - ar, lb = b - br;
    unsigned l;
    asm("cvt.rn.bf16x2.f32 %0, %1, %2;" : "=r"(l) : "f"(lb), "f"(la));
    hi = h; lo = l;
}

// ============ 6. tensor-core sgemm (split-bf16 x3): C = A[M,K] @ W[N,K]^T (+ bias) ============
#define SG_PITCH_H 40
#define SG_PLANE   (128 * SG_PITCH_H)

__global__ __launch_bounds__(256, 1)
void sgemm_tc(const float* __restrict__ A, const float* __restrict__ W,
              const float* __restrict__ bias, float* __restrict__ C,
              int M, int N, int K) {
    __shared__ __nv_bfloat16 sm[4 * SG_PLANE];   // Ahi | Alo | Bhi | Blo  (40 KB)
    __nv_bfloat16* sAhi = sm;
    __nv_bfloat16* sAlo = sm + SG_PLANE;
    __nv_bfloat16* sBhi = sm + 2 * SG_PLANE;
    __nv_bfloat16* sBlo = sm + 3 * SG_PLANE;

    int m0 = blockIdx.x * 128, n0 = blockIdx.y * 128;
    int tid = threadIdx.x, lane = tid & 31, warp = tid >> 5;
    int wm = warp >> 2, wn = warp & 3;
    int g = lane >> 2, tg = lane & 3;

    unsigned aBase = (unsigned)__cvta_generic_to_shared(sAhi);
    unsigned bBase = (unsigned)__cvta_generic_to_shared(sBhi);
    unsigned aAddr[4], bAddr[2];
    {
        int row = wm * 64 + (lane & 15);
        unsigned off = (lane & 16) ? 16u : 0u;
#pragma unroll
        for (int mt = 0; mt < 4; mt++)
            aAddr[mt] = aBase + (unsigned)((row + mt * 16) * 80) + off;
        int nsub = ((lane & 16) >> 1) + (lane & 7);
        unsigned koff = (lane & 8) ? 16u : 0u;
#pragma unroll
        for (int nt2 = 0; nt2 < 2; nt2++)
            bAddr[nt2] = bBase + (unsigned)((wn * 32 + nt2 * 16 + nsub) * 80) + koff;
    }

    float acc[4][4][4];
#pragma unroll
    for (int i = 0; i < 4; i++)
#pragma unroll
        for (int j = 0; j < 4; j++)
#pragma unroll
            for (int r = 0; r < 4; r++) acc[i][j][r] = 0.0f;

    float4 ra[4], rb[4];
#pragma unroll
    for (int it = 0; it < 4; it++) {
        int f = tid * 4 + it * 1024;
        int r = f >> 5, c = f & 31;
        ra[it] = *(const float4*)(A + (size_t)(m0 + r) * K + c);
        rb[it] = *(const float4*)(W + (size_t)(n0 + r) * K + c);
    }

    const int NCHUNK = K / 32;
    for (int kc = 0; kc < NCHUNK; kc++) {
        __syncthreads();
#pragma unroll
        for (int it = 0; it < 4; it++) {
            int f = tid * 4 + it * 1024;
            int r = f >> 5, c = f & 31;
            float4 v = ra[it];
            unsigned h01, l01, h23, l23;
            split_pack(v.x, v.y, h01, l01);
            split_pack(v.z, v.w, h23, l23);
            *(uint2*)(sAhi + r * SG_PITCH_H + c) = make_uint2(h01, h23);
            *(uint2*)(sAlo + r * SG_PITCH_H + c) = make_uint2(l01, l23);
            v = rb[it];
            split_pack(v.x, v.y, h01, l01);
            split_pack(v.z, v.w, h23, l23);
            *(uint2*)(sBhi + r * SG_PITCH_H + c) = make_uint2(h01, h23);
            *(uint2*)(sBlo + r * SG_PITCH_H + c) = make_uint2(l01, l23);
        }
        __syncthreads();
        if (kc + 1 < NCHUNK) {
            int k0 = (kc + 1) * 32;
#pragma unroll
            for (int it = 0; it < 4; it++) {
                int f = tid * 4 + it * 1024;
                int r = f >> 5, c = f & 31;
                ra[it] = *(const float4*)(A + (size_t)(m0 + r) * K + k0 + c);
                rb[it] = *(const float4*)(W + (size_t)(n0 + r) * K + k0 + c);
            }
        }
#pragma unroll
        for (int kk = 0; kk < 2; kk++) {
            unsigned kb = kk * 32;
            unsigned afr[4][2][4], bfr[2][2][4];
#pragma unroll
            for (int mt = 0; mt < 4; mt++) {
                ldsm4(aAddr[mt] + kb,                afr[mt][0][0], afr[mt][0][1], afr[mt][0][2], afr[mt][0][3]);
                ldsm4(aAddr[mt] + kb + SG_PLANE * 2, afr[mt][1][0], afr[mt][1][1], afr[mt][1][2], afr[mt][1][3]);
            }
#pragma unroll
            for (int nt2 = 0; nt2 < 2; nt2++) {
                ldsm4(bAddr[nt2] + kb,                bfr[nt2][0][0], bfr[nt2][0][1], bfr[nt2][0][2], bfr[nt2][0][3]);
                ldsm4(bAddr[nt2] + kb + SG_PLANE * 2, bfr[nt2][1][0], bfr[nt2][1][1], bfr[nt2][1][2], bfr[nt2][1][3]);
            }
#pragma unroll
            for (int mt = 0; mt < 4; mt++)
#pragma unroll
                for (int nt = 0; nt < 4; nt++) {
                    int nt2 = nt >> 1, h = (nt & 1) * 2;
                    float* c = acc[mt][nt];
                    mma_bf16(c, afr[mt][0], bfr[nt2][0][h], bfr[nt2][0][h + 1]);
                    mma_bf16(c, afr[mt][0], bfr[nt2][1][h], bfr[nt2][1][h + 1]);
                    mma_bf16(c, afr[mt][1], bfr[nt2][0][h], bfr[nt2][0][h + 1]);
                }
        }
    }

#pragma unroll
    for (int mt = 0; mt < 4; mt++)
#pragma unroll
        for (int nt = 0; nt < 4; nt++) {
            int m = m0 + wm * 64 + mt * 16 + g;
            int n = n0 + wn * 32 + nt * 8 + tg * 2;
            float2 bv = bias ? *(const float2*)&bias[n] : make_float2(0.f, 0.f);
            float2 o0 = make_float2(acc[mt][nt][0] + bv.x, acc[mt][nt][1] + bv.y);
            float2 o1 = make_float2(acc[mt][nt][2] + bv.x, acc[mt][nt][3] + bv.y);
            *(float2*)(C + (size_t)m * N + n) = o0;
            *(float2*)(C + (size_t)(m + 8) * N + n) = o1;
        }
}

// ============ 7. split-K tensor-core flash attention ============
// Grid 512: block = (bh, half); each block handles 256 keys, all 512 q rows.
// Emits unnormalized partial (o, m, l) to scratch; attn_combine merges halves.
// smem 74.75 KB -> 3 blocks/SM.
#define KP 40
#define KPLANE2 (256 * KP)          // halfs
#define KPL2_B (KPLANE2 * 2)        // 20480
#define VP2 264
#define VPLANE2 (32 * VP2)
#define VPL2_B (VPLANE2 * 2)        // 16896
#define ATTN_TC_SMEM (2 * KPL2_B + 2 * VPL2_B)   // 74752 B

__global__ __launch_bounds__(512, 1)
void attn_tc(const float* __restrict__ qkv, const float* __restrict__ scl,
             const float* __restrict__ bin,
             float* __restrict__ po, float* __restrict__ pm, float* __restrict__ pl) {
    extern __shared__ __nv_bfloat16 smh[];
    __nv_bfloat16* sKhi  = smh;
    __nv_bfloat16* sKlo  = smh + KPLANE2;
    __nv_bfloat16* sVThi = smh + 2 * KPLANE2;
    __nv_bfloat16* sVTlo = smh + 2 * KPLANE2 + VPLANE2;

    int bh = blockIdx.x >> 1, half = blockIdx.x & 1;
    int b = bh >> 3, h = bh & 7;
    int j0 = half * 256;
    const float* base = qkv + (size_t)b * (NNODE * 3 * DIM) + h * HDIM;
    const float* sclb = scl + b * NNODE;
    const float* bq = bin + h * HDIM;
    const float* bk = bin + 256 + h * HDIM;
    const float* bv = bin + 512 + h * HDIM;
    int tid = threadIdx.x, lane = tid & 31, warp = tid >> 5;   // 16 warps
    int g = lane >> 2, tg = lane & 3;
    const float scale = 0.17677669529663687f * 1.4426950408889634f;  // log2e/sqrt(32)

    // stage 256 keys of K (hi/lo) and V^T (hi/lo)
    for (int idx = tid; idx < 256 * 32; idx += 512) {
        int j = idx >> 5, d = idx & 31;
        int jg = j0 + j;
        float sj = sclb[jg];
        float kv = fmaf(sj, base[jg * 768 + 256 + d], bk[d]);
        float vv = fmaf(sj, base[jg * 768 + 512 + d], bv[d]);
        __nv_bfloat16 kh = __float2bfloat16_rn(kv);
        __nv_bfloat16 kl = __float2bfloat16_rn(kv - __bfloat162float(kh));
        __nv_bfloat16 vh = __float2bfloat16_rn(vv);
        __nv_bfloat16 vl = __float2bfloat16_rn(vv - __bfloat162float(vh));
        sKhi[j * KP + d] = kh;  sKlo[j * KP + d] = kl;
        sVThi[d * VP2 + j] = vh; sVTlo[d * VP2 + j] = vl;
    }
    __syncthreads();

    unsigned kBase = (unsigned)__cvta_generic_to_shared(sKhi);
    unsigned vBase = (unsigned)__cvta_generic_to_shared(sVThi);
    int nsub = ((lane & 16) >> 1) + (lane & 7);
    unsigned koff = (lane & 8) ? 16u : 0u;

    for (int chunk = 0; chunk < 2; chunk++) {
        int i0 = chunk * 256 + warp * 16;
        unsigned qh[2][4], ql[2][4];
        const float* qr0 = base + (size_t)(i0 + g) * 768;
        const float* qr8 = base + (size_t)(i0 + g + 8) * 768;
        float si0 = sclb[i0 + g], si8 = sclb[i0 + g + 8];
#pragma unroll
        for (int kf = 0; kf < 2; kf++) {
            int c0 = kf * 16 + 2 * tg;
            float2 v, bb;
            v = *(const float2*)(qr0 + c0);     bb = *(const float2*)(bq + c0);
            split_pack(fmaf(si0, v.x, bb.x) * scale, fmaf(si0, v.y, bb.y) * scale, qh[kf][0], ql[kf][0]);
            v = *(const float2*)(qr8 + c0);
            split_pack(fmaf(si8, v.x, bb.x) * scale, fmaf(si8, v.y, bb.y) * scale, qh[kf][1], ql[kf][1]);
            v = *(const float2*)(qr0 + c0 + 8); bb = *(const float2*)(bq + c0 + 8);
            split_pack(fmaf(si0, v.x, bb.x) * scale, fmaf(si0, v.y, bb.y) * scale, qh[kf][2], ql[kf][2]);
            v = *(const float2*)(qr8 + c0 + 8);
            split_pack(fmaf(si8, v.x, bb.x) * scale, fmaf(si8, v.y, bb.y) * scale, qh[kf][3], ql[kf][3]);
        }

        float m0 = -1e30f, m1 = -1e30f, l0 = 0.0f, l1 = 0.0f;
        float o[4][4];
#pragma unroll
        for (int i = 0; i < 4; i++)
#pragma unroll
            for (int r = 0; r < 4; r++) o[i][r] = 0.0f;

        for (int jt = 0; jt < 4; jt++) {      // 4 x 64 = 256 keys
            float c[8][4];
#pragma unroll
            for (int i = 0; i < 8; i++)
#pragma unroll
                for (int r = 0; r < 4; r++) c[i][r] = 0.0f;

#pragma unroll
            for (int kf = 0; kf < 2; kf++) {
#pragma unroll
                for (int nt2 = 0; nt2 < 4; nt2++) {
                    unsigned bh4[4], bl4[4];
                    unsigned addr = kBase + (unsigned)((jt * 64 + nt2 * 16 + nsub) * (KP * 2)) + kf * 32 + koff;
                    ldsm4(addr, bh4[0], bh4[1], bh4[2], bh4[3]);
                    ldsm4(addr + KPL2_B, bl4[0], bl4[1], bl4[2], bl4[3]);
                    float* ce = c[2 * nt2];
                    float* co = c[2 * nt2 + 1];
                    mma_bf16(ce, qh[kf], bh4[0], bh4[1]);
                    mma_bf16(ce, qh[kf], bl4[0], bl4[1]);
                    mma_bf16(ce, ql[kf], bh4[0], bh4[1]);
                    mma_bf16(co, qh[kf], bh4[2], bh4[3]);
                    mma_bf16(co, qh[kf], bl4[2], bl4[3]);
                    mma_bf16(co, ql[kf], bh4[2], bh4[3]);
                }
            }

            float t0 = -1e30f, t1 = -1e30f;
#pragma unroll
            for (int nt = 0; nt < 8; nt++) {
                t0 = fmaxf(t0, fmaxf(c[nt][0], c[nt][1]));
                t1 = fmaxf(t1, fmaxf(c[nt][2], c[nt][3]));
            }
            t0 = fmaxf(t0, __shfl_xor_sync(0xffffffffu, t0, 1));
            t0 = fmaxf(t0, __shfl_xor_sync(0xffffffffu, t0, 2));
            t1 = fmaxf(t1, __shfl_xor_sync(0xffffffffu, t1, 1));
            t1 = fmaxf(t1, __shfl_xor_sync(0xffffffffu, t1, 2));
            float nm0 = fmaxf(m0, t0), nm1 = fmaxf(m1, t1);
            float f0 = ex2f(m0 - nm0), f1 = ex2f(m1 - nm1);
            m0 = nm0; m1 = nm1;
            l0 *= f0; l1 *= f1;
#pragma unroll
            for (int nt = 0; nt < 4; nt++) {
                o[nt][0] *= f0; o[nt][1] *= f0; o[nt][2] *= f1; o[nt][3] *= f1;
            }
#pragma unroll
            for (int nt = 0; nt < 8; nt++) {
                c[nt][0] = ex2f(c[nt][0] - nm0);
                c[nt][1] = ex2f(c[nt][1] - nm0);
                c[nt][2] = ex2f(c[nt][2] - nm1);
                c[nt][3] = ex2f(c[nt][3] - nm1);
                l0 += c[nt][0] + c[nt][1];
                l1 += c[nt][2] + c[nt][3];
            }

#pragma unroll
            for (int kfp = 0; kfp < 4; kfp++) {
                unsigned ah[4], al[4];
                split_pack(c[2*kfp][0],   c[2*kfp][1],   ah[0], al[0]);
                split_pack(c[2*kfp][2],   c[2*kfp][3],   ah[1], al[1]);
                split_pack(c[2*kfp+1][0], c[2*kfp+1][1], ah[2], al[2]);
                split_pack(c[2*kfp+1][2], c[2*kfp+1][3], ah[3], al[3]);
#pragma unroll
                for (int nt2v = 0; nt2v < 2; nt2v++) {
                    unsigned bh4[4], bl4[4];
                    unsigned addr = vBase + (unsigned)((nt2v * 16 + nsub) * (VP2 * 2))
                                  + (unsigned)((jt * 64 + kfp * 16) * 2) + koff;
                    ldsm4(addr, bh4[0], bh4[1], bh4[2], bh4[3]);
                    ldsm4(addr + VPL2_B, bl4[0], bl4[1], bl4[2], bl4[3]);
                    float* oe = o[2 * nt2v];
                    float* oo = o[2 * nt2v + 1];
                    mma_bf16(oe, ah, bh4[0], bh4[1]);
                    mma_bf16(oe, ah, bl4[0], bl4[1]);
                    mma_bf16(oe, al, bh4[0], bh4[1]);
                    mma_bf16(oo, ah, bh4[2], bh4[3]);
                    mma_bf16(oo, ah, bl4[2], bl4[3]);
                    mma_bf16(oo, al, bh4[2], bh4[3]);
                }
            }
        }

        // partial epilogue: unnormalized o + (m, l) per row
        l0 += __shfl_xor_sync(0xffffffffu, l0, 1);
        l0 += __shfl_xor_sync(0xffffffffu, l0, 2);
        l1 += __shfl_xor_sync(0xffffffffu, l1, 1);
        l1 += __shfl_xor_sync(0xffffffffu, l1, 2);
        size_t pb0 = ((size_t)blockIdx.x * 512 + i0 + g) * 32;
        size_t pb8 = pb0 + 8 * 32;
#pragma unroll
        for (int nt = 0; nt < 4; nt++) {
            int col = nt * 8 + 2 * tg;
            *(float2*)(po + pb0 + col) = make_float2(o[nt][0], o[nt][1]);
            *(float2*)(po + pb8 + col) = make_float2(o[nt][2], o[nt][3]);
        }
        if (tg == 0) {
            pm[blockIdx.x * 512 + i0 + g]     = m0;
            pl[blockIdx.x * 512 + i0 + g]     = l0;
            pm[blockIdx.x * 512 + i0 + g + 8] = m1;
            pl[blockIdx.x * 512 + i0 + g + 8] = l1;
        }
    }
}

// ---------------- 8. split-K combine: merge the two key-halves ----------------
__global__ void attn_combine(const float* __restrict__ po, const float* __restrict__ pm,
                             const float* __restrict__ pl, float* __restrict__ att) {
    int t = blockIdx.x * blockDim.x + threadIdx.x;   // 131072 threads
    int bh = t >> 9, row = t & 511;
    int b = bh >> 3, h = bh & 7;
    size_t i1 = (size_t)(bh * 2 + 0) * 512 + row;
    size_t i2 = (size_t)(bh * 2 + 1) * 512 + row;
    float m1 = pm[i1], m2 = pm[i2], l1 = pl[i1], l2 = pl[i2];
    float m = fmaxf(m1, m2);
    float w1 = ex2f(m1 - m), w2 = ex2f(m2 - m);
    float rs = 1.0f / (l1 * w1 + l2 * w2);
    const float4* o1 = (const float4*)(po + i1 * 32);
    const float4* o2 = (const float4*)(po + i2 * 32);
    float* dst = att + (size_t)(b * 512 + row) * 256 + h * 32;
#pragma unroll
    for (int k = 0; k < 8; k++) {
        float4 a = o1[k], c = o2[k];
        *(float4*)(dst + k * 4) = make_float4((a.x*w1 + c.x*w2) * rs, (a.y*w1 + c.y*w2) * rs,
                                              (a.z*w1 + c.z*w2) * rs, (a.w*w1 + c.w*w2) * rs);
    }
}

// ---------------- launch ----------------
extern "C" void kernel_launch(void* const* d_in, const int* in_sizes, int n_in,
                              void* d_out, int out_size) {
    const float *x = 0, *win = 0, *bin = 0, *wout = 0, *bout = 0;
    const int   *ei = 0;
    int E = 0;
    for (int i = 0; i < n_in; i++) {
        switch (in_sizes[i]) {
            case 4194304: x    = (const float*)d_in[i]; break;
            case 524288:  ei   = (const int*)d_in[i];  E = in_sizes[i] / 2; break;
            case 196608:  win  = (const float*)d_in[i]; break;
            case 768:     bin  = (const float*)d_in[i]; break;
            case 65536:   wout = (const float*)d_in[i]; break;
            case 256:     bout = (const float*)d_in[i]; break;
            default: break;
        }
    }
    float* out = (float*)d_out;

    float *inv, *scl, *qkv, *att, *po, *pmv, *plv;
    unsigned *mA, *mB;
    cudaGetSymbolAddress((void**)&inv, g_inv);
    cudaGetSymbolAddress((void**)&scl, g_scale);
    cudaGetSymbolAddress((void**)&mA,  g_maskA);
    cudaGetSymbolAddress((void**)&mB,  g_maskB);
    cudaGetSymbolAddress((void**)&qkv, g_qkv);
    cudaGetSymbolAddress((void**)&att, g_att);
    cudaGetSymbolAddress((void**)&po,  g_po);
    cudaGetSymbolAddress((void**)&pmv, g_pm);
    cudaGetSymbolAddress((void**)&plv, g_pl);

    static cudaStream_t sB = 0;
    static cudaEvent_t evF = 0, evJ = 0;
    if (!sB) {
        int loPri = 0, hiPri = 0;
        cudaDeviceGetStreamPriorityRange(&loPri, &hiPri);
        cudaStreamCreateWithPriority(&sB, cudaStreamNonBlocking, loPri);
        cudaEventCreateWithFlags(&evF, cudaEventDisableTiming);
        cudaEventCreateWithFlags(&evJ, cudaEventDisableTiming);
        cudaFuncSetAttribute(attn_tc, cudaFuncAttributeMaxDynamicSharedMemorySize, ATTN_TC_SMEM);
    }

    // ---- fork: P = x @ Win^T on low-priority side stream
    cudaEventRecord(evF, 0);
    cudaStreamWaitEvent(sB, evF, 0);
    sgemm_tc<<<dim3(NTOT/128, (3*DIM)/128), 256, 0, sB>>>(x, win, (const float*)0, qkv,
                                                          NTOT, 3*DIM, DIM);

    // ---- graph pipeline on main stream
    norm_kernel<<<NTOT/8, 256>>>(x, inv);
    zero_kernel<<<256, 256>>>(mA, BATCH * GWORDS);
    edge_kernel<<<(E * 8 + 255) / 256, 256>>>(x, ei, inv, mA, E);

    closure_kernel<<<BATCH * 32, 256>>>(mA, mB);
    closure_kernel<<<BATCH * 32, 256>>>(mB, mA);
    closure_kernel<<<BATCH * 32, 256>>>(mA, mB);
    closure_kernel<<<BATCH * 32, 256>>>(mB, mA);
    closure_deg_kernel<<<BATCH * 32, 256>>>(mA, scl);

    // ---- join
    cudaEventRecord(evJ, sB);
    cudaStreamWaitEvent(0, evJ, 0);

    attn_tc<<<BATCH * NHEAD * 2, 512, ATTN_TC_SMEM>>>(qkv, scl, bin, po, pmv, plv);
    attn_combine<<<512, 256>>>(po, pmv, plv, att);
    sgemm_tc<<<dim3(NTOT/128, DIM/128), 256>>>(att, wout, bout, out, NTOT, DIM, DIM);
}

// round 16
// speedup vs baseline: 1.1267x; 1.1267x over previous
#include <cuda_runtime.h>
#include <cuda_bf16.h>

// Problem constants (fixed by setup_inputs)
#define BATCH 32
#define NNODE 512
#define DIM   256
#define NHEAD 8
#define HDIM  32
#define WPR   16            // u32 words per mask row (512/32)
#define GWORDS (NNODE*WPR)  // 8192 words per graph
#define NTOT  (BATCH*NNODE)

// ---------------- scratch (static device globals; no allocations) ----------------
__device__ float     g_inv[NTOT];
__device__ float     g_scale[NTOT];
__device__ unsigned  g_maskA[BATCH*GWORDS];
__device__ unsigned  g_maskB[BATCH*GWORDS];
__device__ float     g_qkv[(size_t)NTOT*3*DIM];   // P = x @ Win^T (unscaled, no bias)
__device__ float     g_att[(size_t)NTOT*DIM];

static __device__ __forceinline__ float warp_sum(float v) {
#pragma unroll
    for (int o = 16; o; o >>= 1) v += __shfl_xor_sync(0xffffffffu, v, o);
    return v;
}
static __device__ __forceinline__ float ex2f(float x) {
    float y; asm("ex2.approx.f32 %0, %1;" : "=f"(y) : "f"(x)); return y;
}

// ---------------- 1. per-node inverse norms (one warp per node) + mask zeroing ----------------
__global__ void norm_kernel(const float* __restrict__ x, float* __restrict__ inv,
                            unsigned* __restrict__ mask) {
    int gt = blockIdx.x * blockDim.x + threadIdx.x;
    int node = gt >> 5;
    int lane = threadIdx.x & 31;
    // fused mask zeroing: 2048 blocks * 256 threads = 524288 = 2*BATCH*GWORDS
    mask[gt & (BATCH * GWORDS / 2 - 1)] = 0u;          // first half
    mask[(BATCH * GWORDS / 2) + (gt & (BATCH * GWORDS / 2 - 1))] = 0u;
    const float4* xr = (const float4*)(x + (size_t)node * DIM);
    float4 a = xr[lane];
    float s = a.x*a.x + a.y*a.y + a.z*a.z + a.w*a.w;
    a = xr[lane + 32];
    s += a.x*a.x + a.y*a.y + a.z*a.z + a.w*a.w;
    s = warp_sum(s);
    if (lane == 0) inv[node] = 1.0f / fmaxf(sqrtf(s), 1e-8f);
}

// ---------------- 3. per-edge cosine sim -> mask bits (8 lanes per edge) ----------------
__global__ void edge_kernel(const float* __restrict__ x, const int* __restrict__ ei,
                            const float* __restrict__ inv, unsigned* __restrict__ mask, int E) {
    int t = blockIdx.x * blockDim.x + threadIdx.x;
    int e = t >> 3, sub = t & 7;
    if (e >= E) return;
    int s = ei[e], d = ei[E + e];
    const float4* xs = (const float4*)(x + (size_t)s * DIM) + sub;
    const float4* xd = (const float4*)(x + (size_t)d * DIM) + sub;
    float acc = 0.0f;
#pragma unroll
    for (int i = 0; i < 8; i++) {
        float4 a = xs[i * 8];
        float4 b = xd[i * 8];
        acc += a.x*b.x + a.y*b.y + a.z*b.z + a.w*b.w;
    }
    acc += __shfl_xor_sync(0xffffffffu, acc, 1);
    acc += __shfl_xor_sync(0xffffffffu, acc, 2);
    acc += __shfl_xor_sync(0xffffffffu, acc, 4);
    if (sub == 0) {
        float sim = acc * inv[s] * inv[d];
        if (sim > 0.1f) {
            int bg = s >> 9, i = s & 511, j = d & 511;
            unsigned* mb = mask + ((size_t)bg << 13);
            atomicOr(&mb[i * WPR + (j >> 5)], 1u << (j & 31));
            atomicOr(&mb[j * WPR + (i >> 5)], 1u << (i & 31));
        }
    }
}

// ---------------- 4. one closure step: dst = src OR src*src ----------------
__global__ void closure_kernel(const unsigned* __restrict__ src, unsigned* __restrict__ dst) {
    __shared__ unsigned sA[GWORDS];           // 32 KB
    int g = blockIdx.x >> 5, ch = blockIdx.x & 31;
    const unsigned* A = src + (size_t)g * GWORDS;
    for (int i = threadIdx.x; i < GWORDS; i += 256) sA[i] = A[i];
    __syncthreads();
    int warp = threadIdx.x >> 5, lane = threadIdx.x & 31, hl = lane & 15;
    bool hi = lane >= 16;
    for (int r = warp; r < 16; r += 8) {
        int i = ch * 16 + r;
        unsigned rowW = sA[i * WPR + hl];
        unsigned acc = rowW;
        for (int w = 0; w < WPR; w++) {
            unsigned bits = __shfl_sync(0xffffffffu, rowW, w);
            while (bits) {
                int k1 = __ffs(bits) - 1; bits &= bits - 1;
                int k2 = -1;
                if (bits) { k2 = __ffs(bits) - 1; bits &= bits - 1; }
                int k = hi ? k2 : k1;
                if (k >= 0) acc |= sA[((w << 5) + k) * WPR + hl];
            }
        }
        acc |= __shfl_xor_sync(0xffffffffu, acc, 16);
        if (!hi) dst[(size_t)g * GWORDS + i * WPR + hl] = acc;
    }
}

// ---------------- 5. final closure step fused with degree->scale ----------------
__global__ void closure_deg_kernel(const unsigned* __restrict__ src, float* __restrict__ scl) {
    __shared__ unsigned sA[GWORDS];           // 32 KB
    int g = blockIdx.x >> 5, ch = blockIdx.x & 31;
    const unsigned* A = src + (size_t)g * GWORDS;
    for (int i = threadIdx.x; i < GWORDS; i += 256) sA[i] = A[i];
    __syncthreads();
    int warp = threadIdx.x >> 5, lane = threadIdx.x & 31, hl = lane & 15;
    bool hi = lane >= 16;
    for (int r = warp; r < 16; r += 8) {
        int i = ch * 16 + r;
        unsigned rowW = sA[i * WPR + hl];
        unsigned acc = rowW;
        for (int w = 0; w < WPR; w++) {
            unsigned bits = __shfl_sync(0xffffffffu, rowW, w);
            while (bits) {
                int k1 = __ffs(bits) - 1; bits &= bits - 1;
                int k2 = -1;
                if (bits) { k2 = __ffs(bits) - 1; bits &= bits - 1; }
                int k = hi ? k2 : k1;
                if (k >= 0) acc |= sA[((w << 5) + k) * WPR + hl];
            }
        }
        acc |= __shfl_xor_sync(0xffffffffu, acc, 16);
        int c = __popc(acc);
#pragma unroll
        for (int o = 16; o; o >>= 1) c += __shfl_xor_sync(0xffffffffu, c, o);
        if (lane == 0) scl[g * NNODE + i] = 1.0f + (float)(c >> 1);
    }
}

// ---- mma.sync helpers ----
static __device__ __forceinline__ void ldsm4(unsigned addr,
    unsigned& r0, unsigned& r1, unsigned& r2, unsigned& r3) {
    asm volatile("ldmatrix.sync.aligned.m8n8.x4.shared.b16 {%0,%1,%2,%3}, [%4];"
                 : "=r"(r0), "=r"(r1), "=r"(r2), "=r"(r3) : "r"(addr));
}
static __device__ __forceinline__ void mma_bf16(float* c, const unsigned* a,
                                                unsigned b0, unsigned b1) {
    asm volatile("mma.sync.aligned.m16n8k16.row.col.f32.bf16.bf16.f32 "
                 "{%0,%1,%2,%3}, {%4,%5,%6,%7}, {%8,%9}, {%0,%1,%2,%3};"
                 : "+f"(c[0]), "+f"(c[1]), "+f"(c[2]), "+f"(c[3])
                 : "r"(a[0]), "r"(a[1]), "r"(a[2]), "r"(a[3]), "r"(b0), "r"(b1));
}
static __device__ __forceinline__ void split_pack(float a, float b, unsigned& hi, unsigned& lo) {
    unsigned h;
    asm("cvt.rn.bf16x2.f32 %0, %1, %2;" : "=r"(h) : "f"(b), "f"(a));  // {hi16:b, lo16:a}
    float ar = __uint_as_float(h << 16);
    float br = __uint_as_float(h & 0xFFFF0000u);
    float la = a - ar, lb = b - br;
    unsigned l;
    asm("cvt.rn.bf16x2.f32 %0, %1, %2;" : "=r"(l) : "f"(lb), "f"(la));
    hi = h; lo = l;
}

// ============ 6. tensor-core sgemm (split-bf16 x3): C = A[M,K] @ W[N,K]^T (+ bias) ============
// __launch_bounds__(256,2): cap regs at 128 so TWO blocks co-reside per SM and
// one block's convert/split phase hides under the other's MMAs.
#define SG_PITCH_H 40
#define SG_PLANE   (128 * SG_PITCH_H)

__global__ __launch_bounds__(256, 2)
void sgemm_tc(const float* __restrict__ A, const float* __restrict__ W,
              const float* __restrict__ bias, float* __restrict__ C,
              int M, int N, int K) {
    __shared__ __nv_bfloat16 sm[4 * SG_PLANE];   // Ahi | Alo | Bhi | Blo  (40 KB)
    __nv_bfloat16* sAhi = sm;
    __nv_bfloat16* sAlo = sm + SG_PLANE;
    __nv_bfloat16* sBhi = sm + 2 * SG_PLANE;
    __nv_bfloat16* sBlo = sm + 3 * SG_PLANE;

    int m0 = blockIdx.x * 128, n0 = blockIdx.y * 128;
    int tid = threadIdx.x, lane = tid & 31, warp = tid >> 5;
    int wm = warp >> 2, wn = warp & 3;
    int g = lane >> 2, tg = lane & 3;

    unsigned aBase = (unsigned)__cvta_generic_to_shared(sAhi);
    unsigned bBase = (unsigned)__cvta_generic_to_shared(sBhi);
    unsigned aAddr[4], bAddr[2];
    {
        int row = wm * 64 + (lane & 15);
        unsigned off = (lane & 16) ? 16u : 0u;
#pragma unroll
        for (int mt = 0; mt < 4; mt++)
            aAddr[mt] = aBase + (unsigned)((row + mt * 16) * 80) + off;
        int nsub = ((lane & 16) >> 1) + (lane & 7);
        unsigned koff = (lane & 8) ? 16u : 0u;
#pragma unroll
        for (int nt2 = 0; nt2 < 2; nt2++)
            bAddr[nt2] = bBase + (unsigned)((wn * 32 + nt2 * 16 + nsub) * 80) + koff;
    }

    float acc[4][4][4];
#pragma unroll
    for (int i = 0; i < 4; i++)
#pragma unroll
        for (int j = 0; j < 4; j++)
#pragma unroll
            for (int r = 0; r < 4; r++) acc[i][j][r] = 0.0f;

    float4 ra[4], rb[4];
#pragma unroll
    for (int it = 0; it < 4; it++) {
        int f = tid * 4 + it * 1024;
        int r = f >> 5, c = f & 31;
        ra[it] = *(const float4*)(A + (size_t)(m0 + r) * K + c);
        rb[it] = *(const float4*)(W + (size_t)(n0 + r) * K + c);
    }

    const int NCHUNK = K / 32;
    for (int kc = 0; kc < NCHUNK; kc++) {
        __syncthreads();
#pragma unroll
        for (int it = 0; it < 4; it++) {
            int f = tid * 4 + it * 1024;
            int r = f >> 5, c = f & 31;
            float4 v = ra[it];
            unsigned h01, l01, h23, l23;
            split_pack(v.x, v.y, h01, l01);
            split_pack(v.z, v.w, h23, l23);
            *(uint2*)(sAhi + r * SG_PITCH_H + c) = make_uint2(h01, h23);
            *(uint2*)(sAlo + r * SG_PITCH_H + c) = make_uint2(l01, l23);
            v = rb[it];
            split_pack(v.x, v.y, h01, l01);
            split_pack(v.z, v.w, h23, l23);
            *(uint2*)(sBhi + r * SG_PITCH_H + c) = make_uint2(h01, h23);
            *(uint2*)(sBlo + r * SG_PITCH_H + c) = make_uint2(l01, l23);
        }
        __syncthreads();
        if (kc + 1 < NCHUNK) {
            int k0 = (kc + 1) * 32;
#pragma unroll
            for (int it = 0; it < 4; it++) {
                int f = tid * 4 + it * 1024;
                int r = f >> 5, c = f & 31;
                ra[it] = *(const float4*)(A + (size_t)(m0 + r) * K + k0 + c);
                rb[it] = *(const float4*)(W + (size_t)(n0 + r) * K + k0 + c);
            }
        }
#pragma unroll
        for (int kk = 0; kk < 2; kk++) {
            unsigned kb = kk * 32;
            unsigned afr[4][2][4], bfr[2][2][4];
#pragma unroll
            for (int mt = 0; mt < 4; mt++) {
                ldsm4(aAddr[mt] + kb,                afr[mt][0][0], afr[mt][0][1], afr[mt][0][2], afr[mt][0][3]);
                ldsm4(aAddr[mt] + kb + SG_PLANE * 2, afr[mt][1][0], afr[mt][1][1], afr[mt][1][2], afr[mt][1][3]);
            }
#pragma unroll
            for (int nt2 = 0; nt2 < 2; nt2++) {
                ldsm4(bAddr[nt2] + kb,                bfr[nt2][0][0], bfr[nt2][0][1], bfr[nt2][0][2], bfr[nt2][0][3]);
                ldsm4(bAddr[nt2] + kb + SG_PLANE * 2, bfr[nt2][1][0], bfr[nt2][1][1], bfr[nt2][1][2], bfr[nt2][1][3]);
            }
#pragma unroll
            for (int mt = 0; mt < 4; mt++)
#pragma unroll
                for (int nt = 0; nt < 4; nt++) {
                    int nt2 = nt >> 1, h = (nt & 1) * 2;
                    float* c = acc[mt][nt];
                    mma_bf16(c, afr[mt][0], bfr[nt2][0][h], bfr[nt2][0][h + 1]);
                    mma_bf16(c, afr[mt][0], bfr[nt2][1][h], bfr[nt2][1][h + 1]);
                    mma_bf16(c, afr[mt][1], bfr[nt2][0][h], bfr[nt2][0][h + 1]);
                }
        }
    }

#pragma unroll
    for (int mt = 0; mt < 4; mt++)
#pragma unroll
        for (int nt = 0; nt < 4; nt++) {
            int m = m0 + wm * 64 + mt * 16 + g;
            int n = n0 + wn * 32 + nt * 8 + tg * 2;
            float2 bv = bias ? *(const float2*)&bias[n] : make_float2(0.f, 0.f);
            float2 o0 = make_float2(acc[mt][nt][0] + bv.x, acc[mt][nt][1] + bv.y);
            float2 o1 = make_float2(acc[mt][nt][2] + bv.x, acc[mt][nt][3] + bv.y);
            *(float2*)(C + (size_t)m * N + n) = o0;
            *(float2*)(C + (size_t)(m + 8) * N + n) = o1;
        }
}

// ============ 7. tensor-core flash attention, 512 threads (16 warps) per (b,h) ============
// (R14 version: grid 256, full 512 keys in smem, ex2 log2-domain softmax)
#define KP 40
#define KPLANE (512 * KP)
#define KPL_B (KPLANE * 2)         // 40960
#define VP 520
#define VPLANE (32 * VP)
#define VPL_B (VPLANE * 2)         // 33280
#define ATTN_TC_SMEM (2 * KPL_B + 2 * VPL_B)   // 148480 B

__global__ __launch_bounds__(512, 1)
void attn_tc(const float* __restrict__ qkv, const float* __restrict__ scl,
             const float* __restrict__ bin, float* __restrict__ att) {
    extern __shared__ __nv_bfloat16 smh[];
    __nv_bfloat16* sKhi  = smh;
    __nv_bfloat16* sKlo  = smh + KPLANE;
    __nv_bfloat16* sVThi = smh + 2 * KPLANE;
    __nv_bfloat16* sVTlo = smh + 2 * KPLANE + VPLANE;

    int b = blockIdx.x >> 3, h = blockIdx.x & 7;
    const float* base = qkv + (size_t)b * (NNODE * 3 * DIM) + h * HDIM;
    const float* sclb = scl + b * NNODE;
    const float* bq = bin + h * HDIM;
    const float* bk = bin + 256 + h * HDIM;
    const float* bv = bin + 512 + h * HDIM;
    int tid = threadIdx.x, lane = tid & 31, warp = tid >> 5;   // 16 warps
    int g = lane >> 2, tg = lane & 3;
    const float scale = 0.17677669529663687f * 1.4426950408889634f;  // log2e/sqrt(32)

    for (int idx = tid; idx < 512 * 32; idx += 512) {
        int j = idx >> 5, d = idx & 31;
        float sj = sclb[j];
        float kv = fmaf(sj, base[j * 768 + 256 + d], bk[d]);
        float vv = fmaf(sj, base[j * 768 + 512 + d], bv[d]);
        __nv_bfloat16 kh = __float2bfloat16_rn(kv);
        __nv_bfloat16 kl = __float2bfloat16_rn(kv - __bfloat162float(kh));
        __nv_bfloat16 vh = __float2bfloat16_rn(vv);
        __nv_bfloat16 vl = __float2bfloat16_rn(vv - __bfloat162float(vh));
        sKhi[j * KP + d] = kh;  sKlo[j * KP + d] = kl;
        sVThi[d * VP + j] = vh; sVTlo[d * VP + j] = vl;
    }
    __syncthreads();

    unsigned kBase = (unsigned)__cvta_generic_to_shared(sKhi);
    unsigned vBase = (unsigned)__cvta_generic_to_shared(sVThi);
    int nsub = ((lane & 16) >> 1) + (lane & 7);
    unsigned koff = (lane & 8) ? 16u : 0u;

    for (int chunk = 0; chunk < 2; chunk++) {
        int i0 = chunk * 256 + warp * 16;
        unsigned qh[2][4], ql[2][4];
        const float* qr0 = base + (size_t)(i0 + g) * 768;
        const float* qr8 = base + (size_t)(i0 + g + 8) * 768;
        float si0 = sclb[i0 + g], si8 = sclb[i0 + g + 8];
#pragma unroll
        for (int kf = 0; kf < 2; kf++) {
            int c0 = kf * 16 + 2 * tg;
            float2 v, bb;
            v = *(const float2*)(qr0 + c0);     bb = *(const float2*)(bq + c0);
            split_pack(fmaf(si0, v.x, bb.x) * scale, fmaf(si0, v.y, bb.y) * scale, qh[kf][0], ql[kf][0]);
            v = *(const float2*)(qr8 + c0);
            split_pack(fmaf(si8, v.x, bb.x) * scale, fmaf(si8, v.y, bb.y) * scale, qh[kf][1], ql[kf][1]);
            v = *(const float2*)(qr0 + c0 + 8); bb = *(const float2*)(bq + c0 + 8);
            split_pack(fmaf(si0, v.x, bb.x) * scale, fmaf(si0, v.y, bb.y) * scale, qh[kf][2], ql[kf][2]);
            v = *(const float2*)(qr8 + c0 + 8);
            split_pack(fmaf(si8, v.x, bb.x) * scale, fmaf(si8, v.y, bb.y) * scale, qh[kf][3], ql[kf][3]);
        }

        float m0 = -1e30f, m1 = -1e30f, l0 = 0.0f, l1 = 0.0f;
        float o[4][4];
#pragma unroll
        for (int i = 0; i < 4; i++)
#pragma unroll
            for (int r = 0; r < 4; r++) o[i][r] = 0.0f;

        for (int jt = 0; jt < 8; jt++) {
            float c[8][4];
#pragma unroll
            for (int i = 0; i < 8; i++)
#pragma unroll
                for (int r = 0; r < 4; r++) c[i][r] = 0.0f;

#pragma unroll
            for (int kf = 0; kf < 2; kf++) {
#pragma unroll
                for (int nt2 = 0; nt2 < 4; nt2++) {
                    unsigned bh[4], bl[4];
                    unsigned addr = kBase + (unsigned)((jt * 64 + nt2 * 16 + nsub) * (KP * 2)) + kf * 32 + koff;
                    ldsm4(addr, bh[0], bh[1], bh[2], bh[3]);
                    ldsm4(addr + KPL_B, bl[0], bl[1], bl[2], bl[3]);
                    float* ce = c[2 * nt2];
                    float* co = c[2 * nt2 + 1];
                    mma_bf16(ce, qh[kf], bh[0], bh[1]);
                    mma_bf16(ce, qh[kf], bl[0], bl[1]);
                    mma_bf16(ce, ql[kf], bh[0], bh[1]);
                    mma_bf16(co, qh[kf], bh[2], bh[3]);
                    mma_bf16(co, qh[kf], bl[2], bl[3]);
                    mma_bf16(co, ql[kf], bh[2], bh[3]);
                }
            }

            float t0 = -1e30f, t1 = -1e30f;
#pragma unroll
            for (int nt = 0; nt < 8; nt++) {
                t0 = fmaxf(t0, fmaxf(c[nt][0], c[nt][1]));
                t1 = fmaxf(t1, fmaxf(c[nt][2], c[nt][3]));
            }
            t0 = fmaxf(t0, __shfl_xor_sync(0xffffffffu, t0, 1));
            t0 = fmaxf(t0, __shfl_xor_sync(0xffffffffu, t0, 2));
            t1 = fmaxf(t1, __shfl_xor_sync(0xffffffffu, t1, 1));
            t1 = fmaxf(t1, __shfl_xor_sync(0xffffffffu, t1, 2));
            float nm0 = fmaxf(m0, t0), nm1 = fmaxf(m1, t1);
            float f0 = ex2f(m0 - nm0), f1 = ex2f(m1 - nm1);
            m0 = nm0; m1 = nm1;
            l0 *= f0; l1 *= f1;
#pragma unroll
            for (int nt = 0; nt < 4; nt++) {
                o[nt][0] *= f0; o[nt][1] *= f0; o[nt][2] *= f1; o[nt][3] *= f1;
            }
#pragma unroll
            for (int nt = 0; nt < 8; nt++) {
                c[nt][0] = ex2f(c[nt][0] - nm0);
                c[nt][1] = ex2f(c[nt][1] - nm0);
                c[nt][2] = ex2f(c[nt][2] - nm1);
                c[nt][3] = ex2f(c[nt][3] - nm1);
                l0 += c[nt][0] + c[nt][1];
                l1 += c[nt][2] + c[nt][3];
            }

#pragma unroll
            for (int kfp = 0; kfp < 4; kfp++) {
                unsigned ah[4], al[4];
                split_pack(c[2*kfp][0],   c[2*kfp][1],   ah[0], al[0]);
                split_pack(c[2*kfp][2],   c[2*kfp][3],   ah[1], al[1]);
                split_pack(c[2*kfp+1][0], c[2*kfp+1][1], ah[2], al[2]);
                split_pack(c[2*kfp+1][2], c[2*kfp+1][3], ah[3], al[3]);
#pragma unroll
                for (int nt2v = 0; nt2v < 2; nt2v++) {
                    unsigned bh[4], bl[4];
                    unsigned addr = vBase + (unsigned)((nt2v * 16 + nsub) * (VP * 2))
                                  + (unsigned)((jt * 64 + kfp * 16) * 2) + koff;
                    ldsm4(addr, bh[0], bh[1], bh[2], bh[3]);
                    ldsm4(addr + VPL_B, bl[0], bl[1], bl[2], bl[3]);
                    float* oe = o[2 * nt2v];
                    float* oo = o[2 * nt2v + 1];
                    mma_bf16(oe, ah, bh[0], bh[1]);
                    mma_bf16(oe, ah, bl[0], bl[1]);
                    mma_bf16(oe, al, bh[0], bh[1]);
                    mma_bf16(oo, ah, bh[2], bh[3]);
                    mma_bf16(oo, ah, bl[2], bl[3]);
                    mma_bf16(oo, al, bh[2], bh[3]);
                }
            }
        }

        l0 += __shfl_xor_sync(0xffffffffu, l0, 1);
        l0 += __shfl_xor_sync(0xffffffffu, l0, 2);
        l1 += __shfl_xor_sync(0xffffffffu, l1, 1);
        l1 += __shfl_xor_sync(0xffffffffu, l1, 2);
        float rs0 = 1.0f / l0, rs1 = 1.0f / l1;
        size_t ob0 = (size_t)(b * 512 + i0 + g) * DIM + h * HDIM;
        size_t ob8 = (size_t)(b * 512 + i0 + g + 8) * DIM + h * HDIM;
#pragma unroll
        for (int nt = 0; nt < 4; nt++) {
            int col = nt * 8 + 2 * tg;
            *(float2*)(att + ob0 + col) = make_float2(o[nt][0] * rs0, o[nt][1] * rs0);
            *(float2*)(att + ob8 + col) = make_float2(o[nt][2] * rs1, o[nt][3] * rs1);
        }
    }
}

// ---------------- launch ----------------
extern "C" void kernel_launch(void* const* d_in, const int* in_sizes, int n_in,
                              void* d_out, int out_size) {
    const float *x = 0, *win = 0, *bin = 0, *wout = 0, *bout = 0;
    const int   *ei = 0;
    int E = 0;
    for (int i = 0; i < n_in; i++) {
        switch (in_sizes[i]) {
            case 4194304: x    = (const float*)d_in[i]; break;
            case 524288:  ei   = (const int*)d_in[i];  E = in_sizes[i] / 2; break;
            case 196608:  win  = (const float*)d_in[i]; break;
            case 768:     bin  = (const float*)d_in[i]; break;
            case 65536:   wout = (const float*)d_in[i]; break;
            case 256:     bout = (const float*)d_in[i]; break;
            default: break;
        }
    }
    float* out = (float*)d_out;

    float *inv, *scl, *qkv, *att;
    unsigned *mA, *mB;
    cudaGetSymbolAddress((void**)&inv, g_inv);
    cudaGetSymbolAddress((void**)&scl, g_scale);
    cudaGetSymbolAddress((void**)&mA,  g_maskA);
    cudaGetSymbolAddress((void**)&mB,  g_maskB);
    cudaGetSymbolAddress((void**)&qkv, g_qkv);
    cudaGetSymbolAddress((void**)&att, g_att);

    static cudaStream_t sB = 0;
    static cudaEvent_t evF = 0, evJ = 0;
    if (!sB) {
        int loPri = 0, hiPri = 0;
        cudaDeviceGetStreamPriorityRange(&loPri, &hiPri);
        cudaStreamCreateWithPriority(&sB, cudaStreamNonBlocking, loPri);
        cudaEventCreateWithFlags(&evF, cudaEventDisableTiming);
        cudaEventCreateWithFlags(&evJ, cudaEventDisableTiming);
        cudaFuncSetAttribute(attn_tc, cudaFuncAttributeMaxDynamicSharedMemorySize, ATTN_TC_SMEM);
    }

    // ---- fork: P = x @ Win^T on low-priority side stream
    cudaEventRecord(evF, 0);
    cudaStreamWaitEvent(sB, evF, 0);
    sgemm_tc<<<dim3(NTOT/128, (3*DIM)/128), 256, 0, sB>>>(x, win, (const float*)0, qkv,
                                                          NTOT, 3*DIM, DIM);

    // ---- graph pipeline on main stream (zeroing fused into norm)
    norm_kernel<<<NTOT/8, 256>>>(x, inv, mA);
    edge_kernel<<<(E * 8 + 255) / 256, 256>>>(x, ei, inv, mA, E);

    closure_kernel<<<BATCH * 32, 256>>>(mA, mB);
    closure_kernel<<<BATCH * 32, 256>>>(mB, mA);
    closure_kernel<<<BATCH * 32, 256>>>(mA, mB);
    closure_kernel<<<BATCH * 32, 256>>>(mB, mA);
    closure_deg_kernel<<<BATCH * 32, 256>>>(mA, scl);

    // ---- join
    cudaEventRecord(evJ, sB);
    cudaStreamWaitEvent(0, evJ, 0);

    attn_tc<<<BATCH * NHEAD, 512, ATTN_TC_SMEM>>>(qkv, scl, bin, att);
    sgemm_tc<<<dim3(NTOT/128, DIM/128), 256>>>(att, wout, bout, out, NTOT, DIM, DIM);
}